// round 3
// baseline (speedup 1.0000x reference)
#include <cuda_runtime.h>

// EGNN forward, N=50000 nodes, E=1.6M edges, H=32, DX=16, L=2.
// R3: counting-sort edges by row -> CSR; edge kernel writes per-edge m/trans
//     with plain stores (no atomics); warp-per-node aggregation kernel.

#define H    32
#define DX   16
#define NMAX 50048
#define EMAX 1605632

__device__ __align__(16) float g_x[NMAX * DX];
__device__ __align__(16) float g_h[NMAX * H];
__device__ __align__(16) float g_A[NMAX * H];
__device__ __align__(16) float g_B[NMAX * H];
__device__ __align__(16) float g_magg[NMAX * H];
__device__ __align__(16) float g_tagg[NMAX * DX];
__device__ float g_cnt[NMAX];

__device__ int g_deg[NMAX];
__device__ int g_rowptr[NMAX + 1];
__device__ int g_cursor[NMAX];
__device__ int g_srow[EMAX];
__device__ int g_scol[EMAX];
__device__ __align__(16) float g_m[(size_t)EMAX * H];
__device__ __align__(16) float g_t[(size_t)EMAX * DX];
__device__ int g_dummy;

__device__ __forceinline__ float silu_f(float v) {
    return v * (1.0f / (1.0f + __expf(-v)));
}

// ---------------------------------------------------------------------------
// init: x0, h0, A0/B0, zero degree histogram
// ---------------------------------------------------------------------------
__global__ __launch_bounds__(128, 4) void init_kernel(
    const float* __restrict__ attrs,
    const float* __restrict__ pos,
    const float* __restrict__ projW,
    const float* __restrict__ embW,
    const float* __restrict__ embB,
    const float* __restrict__ eW1,    // layer0 edge_W1 [32][68]
    const float* __restrict__ eb1,
    int n)
{
    __shared__ __align__(16) float sWa[H][H];   // [k][j] transposed
    __shared__ __align__(16) float sWb[H][H];
    for (int idx = threadIdx.x; idx < H * H; idx += 128) {
        int j = idx >> 5, k = idx & 31;
        sWa[k][j] = eW1[j * 68 + k];
        sWb[k][j] = eW1[j * 68 + 32 + k];
    }
    __syncthreads();

    int i = blockIdx.x * 128 + threadIdx.x;
    if (i >= n) return;

    g_deg[i] = 0;

    float p0 = pos[i * 3 + 0], p1 = pos[i * 3 + 1], p2 = pos[i * 3 + 2];
    float xv[DX];
#pragma unroll
    for (int j = 0; j < DX; j++)
        xv[j] = projW[j * 3 + 0] * p0 + projW[j * 3 + 1] * p1 + projW[j * 3 + 2] * p2;

    float4* xo = (float4*)&g_x[i * DX];
#pragma unroll
    for (int q = 0; q < 4; q++)
        xo[q] = make_float4(xv[4 * q], xv[4 * q + 1], xv[4 * q + 2], xv[4 * q + 3]);

    float a0 = attrs[i * 3 + 0], a1 = attrs[i * 3 + 1], a2 = attrs[i * 3 + 2];
    float hv[H];
#pragma unroll
    for (int j = 0; j < H; j++)
        hv[j] = embW[j * 3 + 0] * a0 + embW[j * 3 + 1] * a1 + embW[j * 3 + 2] * a2 + embB[j];

    float4* ho = (float4*)&g_h[i * H];
#pragma unroll
    for (int q = 0; q < 8; q++)
        ho[q] = make_float4(hv[4 * q], hv[4 * q + 1], hv[4 * q + 2], hv[4 * q + 3]);

    float Av[H], Bv[H];
#pragma unroll
    for (int j = 0; j < H; j++) { Av[j] = eb1[j]; Bv[j] = 0.0f; }
#pragma unroll
    for (int k = 0; k < H; k++) {
        float hk = hv[k];
        const float4* wa = (const float4*)&sWa[k][0];
        const float4* wb = (const float4*)&sWb[k][0];
#pragma unroll
        for (int q = 0; q < 8; q++) {
            float4 a = wa[q], b = wb[q];
            Av[4 * q + 0] += a.x * hk; Av[4 * q + 1] += a.y * hk;
            Av[4 * q + 2] += a.z * hk; Av[4 * q + 3] += a.w * hk;
            Bv[4 * q + 0] += b.x * hk; Bv[4 * q + 1] += b.y * hk;
            Bv[4 * q + 2] += b.z * hk; Bv[4 * q + 3] += b.w * hk;
        }
    }
    float4* Ao = (float4*)&g_A[i * H];
    float4* Bo = (float4*)&g_B[i * H];
#pragma unroll
    for (int q = 0; q < 8; q++) {
        Ao[q] = make_float4(Av[4 * q], Av[4 * q + 1], Av[4 * q + 2], Av[4 * q + 3]);
        Bo[q] = make_float4(Bv[4 * q], Bv[4 * q + 1], Bv[4 * q + 2], Bv[4 * q + 3]);
    }
}

// ---------------------------------------------------------------------------
// sort phase 1: degree histogram
// ---------------------------------------------------------------------------
__global__ void hist_kernel(const int* __restrict__ ei, int E)
{
    int e = blockIdx.x * blockDim.x + threadIdx.x;
    if (e < E) atomicAdd(&g_deg[ei[e]], 1);
}

// ---------------------------------------------------------------------------
// sort phase 2: exclusive prefix sum over degrees (single block)
// ---------------------------------------------------------------------------
#define SCAN_T 1024
#define BINS_PER_T 49   // 1024*49 = 50176 >= NMAX

__global__ __launch_bounds__(SCAN_T) void scan_kernel(int n, int E)
{
    __shared__ int s_sum[SCAN_T];
    int t = threadIdx.x;
    int base = t * BINS_PER_T;

    int sum = 0;
#pragma unroll 7
    for (int r = 0; r < BINS_PER_T; r++) {
        int b = base + r;
        if (b < n) sum += g_deg[b];
    }
    s_sum[t] = sum;
    __syncthreads();

    // Hillis-Steele inclusive scan
    for (int d = 1; d < SCAN_T; d <<= 1) {
        int v = (t >= d) ? s_sum[t - d] : 0;
        __syncthreads();
        s_sum[t] += v;
        __syncthreads();
    }

    int run = (t > 0) ? s_sum[t - 1] : 0;  // exclusive offset for this thread
    for (int r = 0; r < BINS_PER_T; r++) {
        int b = base + r;
        if (b < n) {
            g_rowptr[b] = run;
            g_cursor[b] = run;
            run += g_deg[b];
        }
    }
    if (t == 0) g_rowptr[n] = E;
}

// ---------------------------------------------------------------------------
// sort phase 3: scatter edges into row-sorted order
// ---------------------------------------------------------------------------
__global__ void scatter_kernel(const int* __restrict__ ei, int E)
{
    int e = blockIdx.x * blockDim.x + threadIdx.x;
    if (e >= E) return;
    int row = ei[e];
    int col = ei[E + e];
    int p = atomicAdd(&g_cursor[row], 1);
    g_srow[p] = row;
    g_scol[p] = col;
}

// nop: aligns ncu -s 5 capture onto the first edge kernel
__global__ void nop_kernel() { if (blockIdx.x == 1u << 30) g_dummy = 1; }

// ---------------------------------------------------------------------------
// edge kernel over sorted edges: fused MLPs, plain streaming stores
// ---------------------------------------------------------------------------
#define ETPB 128

__global__ __launch_bounds__(ETPB, 4) void edge_kernel(
    int E,
    const float* __restrict__ pos,
    const float* __restrict__ W1,   // [32][68], cols 64..67 used
    const float* __restrict__ W2,   // [32][32]
    const float* __restrict__ b2,
    const float* __restrict__ cW1,  // [32][32]
    const float* __restrict__ cb1,
    const float* __restrict__ cW2)  // [32]
{
    __shared__ __align__(16) float s_W2t[H][H];   // [k][j]
    __shared__ __align__(16) float s_cW1t[H][H];  // [k][j]
    __shared__ float s_wr[H];
    __shared__ float s_we[3][H];
    __shared__ float s_b2[H];
    __shared__ float s_cb1[H];
    __shared__ float s_cw2[H];

    for (int idx = threadIdx.x; idx < H * H; idx += ETPB) {
        int j = idx >> 5, k = idx & 31;
        s_W2t[k][j]  = W2[idx];
        s_cW1t[k][j] = cW1[idx];
    }
    if (threadIdx.x < H) {
        int j = threadIdx.x;
        s_wr[j]    = W1[j * 68 + 64];
        s_we[0][j] = W1[j * 68 + 65];
        s_we[1][j] = W1[j * 68 + 66];
        s_we[2][j] = W1[j * 68 + 67];
        s_b2[j]  = b2[j];
        s_cb1[j] = cb1[j];
        s_cw2[j] = cW2[j];
    }
    __syncthreads();

    int e = blockIdx.x * ETPB + threadIdx.x;
    if (e >= E) return;

    int row = g_srow[e];
    int col = g_scol[e];

    float ea0 = pos[row * 3 + 0] - pos[col * 3 + 0];
    float ea1 = pos[row * 3 + 1] - pos[col * 3 + 1];
    float ea2 = pos[row * 3 + 2] - pos[col * 3 + 2];

    float cd[DX];
    const float4* xr = (const float4*)&g_x[row * DX];
    const float4* xc = (const float4*)&g_x[col * DX];
    float radial = 0.0f;
#pragma unroll
    for (int q = 0; q < 4; q++) {
        float4 a = xr[q], b = xc[q];
        float d0 = a.x - b.x, d1 = a.y - b.y, d2 = a.z - b.z, d3 = a.w - b.w;
        cd[4 * q + 0] = d0; cd[4 * q + 1] = d1; cd[4 * q + 2] = d2; cd[4 * q + 3] = d3;
        radial += d0 * d0 + d1 * d1 + d2 * d2 + d3 * d3;
    }

    // layer-1 (A/B factored)
    float acc[H];
    {
        const float4* Ar = (const float4*)&g_A[row * H];
        const float4* Bc = (const float4*)&g_B[col * H];
#pragma unroll
        for (int q = 0; q < 8; q++) {
            float4 a = Ar[q], b = Bc[q];
            acc[4 * q + 0] = a.x + b.x; acc[4 * q + 1] = a.y + b.y;
            acc[4 * q + 2] = a.z + b.z; acc[4 * q + 3] = a.w + b.w;
        }
#pragma unroll
        for (int j = 0; j < H; j++) {
            acc[j] += s_wr[j] * radial + s_we[0][j] * ea0 + s_we[1][j] * ea1 + s_we[2][j] * ea2;
            acc[j] = silu_f(acc[j]);
        }
    }

    // layer-2
    float m[H];
    {
#pragma unroll
        for (int j = 0; j < H; j++) m[j] = s_b2[j];
#pragma unroll
        for (int k = 0; k < H; k++) {
            float mk = acc[k];
            const float4* wr4 = (const float4*)&s_W2t[k][0];
#pragma unroll
            for (int q = 0; q < 8; q++) {
                float4 w = wr4[q];
                m[4 * q + 0] += w.x * mk; m[4 * q + 1] += w.y * mk;
                m[4 * q + 2] += w.z * mk; m[4 * q + 3] += w.w * mk;
            }
        }
#pragma unroll
        for (int j = 0; j < H; j++) m[j] = silu_f(m[j]);
    }

    // coord head
    float cm;
    {
        float cacc[H];
#pragma unroll
        for (int j = 0; j < H; j++) cacc[j] = s_cb1[j];
#pragma unroll
        for (int k = 0; k < H; k++) {
            float mk = m[k];
            const float4* wr4 = (const float4*)&s_cW1t[k][0];
#pragma unroll
            for (int q = 0; q < 8; q++) {
                float4 w = wr4[q];
                cacc[4 * q + 0] += w.x * mk; cacc[4 * q + 1] += w.y * mk;
                cacc[4 * q + 2] += w.z * mk; cacc[4 * q + 3] += w.w * mk;
            }
        }
        cm = 0.0f;
#pragma unroll
        for (int j = 0; j < H; j++) cm += s_cw2[j] * silu_f(cacc[j]);
    }

    // streaming stores (no atomics)
    float4* mo = (float4*)&g_m[(size_t)e * H];
#pragma unroll
    for (int q = 0; q < 8; q++)
        mo[q] = make_float4(m[4 * q], m[4 * q + 1], m[4 * q + 2], m[4 * q + 3]);

    float4* to = (float4*)&g_t[(size_t)e * DX];
#pragma unroll
    for (int q = 0; q < 4; q++)
        to[q] = make_float4(cd[4 * q] * cm, cd[4 * q + 1] * cm,
                            cd[4 * q + 2] * cm, cd[4 * q + 3] * cm);
}

// ---------------------------------------------------------------------------
// aggregation: warp per node over its contiguous sorted-edge range
// ---------------------------------------------------------------------------
__global__ __launch_bounds__(128, 8) void agg_kernel(int n)
{
    int wid = (blockIdx.x * 128 + threadIdx.x) >> 5;
    int lane = threadIdx.x & 31;
    if (wid >= n) return;

    int s = g_rowptr[wid];
    int t = g_rowptr[wid + 1];

    // messages: lane = component, coalesced 128B per iteration
    float a0 = 0.0f, a1 = 0.0f;
    int e = s;
    for (; e + 1 < t; e += 2) {
        a0 += g_m[(size_t)e * H + lane];
        a1 += g_m[(size_t)(e + 1) * H + lane];
    }
    if (e < t) a0 += g_m[(size_t)e * H + lane];
    g_magg[wid * H + lane] = a0 + a1;

    // trans: two edges per iteration (half-warp each), then combine
    int comp = lane & 15;
    int half = lane >> 4;
    float tacc = 0.0f;
    for (int it = half; it < t - s; it += 2)
        tacc += g_t[(size_t)(s + it) * DX + comp];
    tacc += __shfl_xor_sync(0xffffffffu, tacc, 16);
    if (lane < 16) g_tagg[wid * DX + lane] = tacc;

    if (lane == 0) g_cnt[wid] = (float)(t - s);
}

// ---------------------------------------------------------------------------
// node kernel
// ---------------------------------------------------------------------------
#define NTPB 128

__global__ __launch_bounds__(NTPB, 4) void node_kernel(
    const float* __restrict__ nW1,   // [32][64]
    const float* __restrict__ nb1,
    const float* __restrict__ nW2,   // [32][32]
    const float* __restrict__ nb2,
    const float* __restrict__ eW1n,  // next-layer edge_W1 [32][68] or null
    const float* __restrict__ eb1n,
    const float* __restrict__ linW,  // [3][16] or null
    float* __restrict__ out,
    int n)
{
    __shared__ __align__(16) float sN1t[2 * H][H];  // [k][j]
    __shared__ __align__(16) float sN2t[H][H];      // [k][j]
    __shared__ __align__(16) float sEAt[H][H];      // [k][j]
    __shared__ __align__(16) float sEBt[H][H];

    int i = blockIdx.x * NTPB + threadIdx.x;
    bool active = (i < n);

    // issue per-node gathers early (overlap with weight staging)
    float cnt = 0.f;
    float4 xr[4], tr[4], hr[8], mr[8];
    if (active) {
        cnt = g_cnt[i];
        const float4* xp = (const float4*)&g_x[i * DX];
        const float4* tp = (const float4*)&g_tagg[i * DX];
        const float4* hp = (const float4*)&g_h[i * H];
        const float4* mp = (const float4*)&g_magg[i * H];
#pragma unroll
        for (int q = 0; q < 4; q++) { xr[q] = xp[q]; tr[q] = tp[q]; }
#pragma unroll
        for (int q = 0; q < 8; q++) { hr[q] = hp[q]; mr[q] = mp[q]; }
    }

    for (int idx = threadIdx.x; idx < H * 2 * H; idx += NTPB) {
        int j = idx >> 6, k = idx & 63;
        sN1t[k][j] = nW1[idx];
    }
    for (int idx = threadIdx.x; idx < H * H; idx += NTPB) {
        int j = idx >> 5, k = idx & 31;
        sN2t[k][j] = nW2[idx];
        if (eW1n) {
            sEAt[k][j] = eW1n[j * 68 + k];
            sEBt[k][j] = eW1n[j * 68 + 32 + k];
        }
    }
    __syncthreads();

    if (!active) return;

    float inv = 1.0f / fmaxf(cnt, 1.0f);

    float xv[DX];
#pragma unroll
    for (int q = 0; q < 4; q++) {
        xv[4 * q + 0] = xr[q].x + tr[q].x * inv;
        xv[4 * q + 1] = xr[q].y + tr[q].y * inv;
        xv[4 * q + 2] = xr[q].z + tr[q].z * inv;
        xv[4 * q + 3] = xr[q].w + tr[q].w * inv;
    }
    float4* xp = (float4*)&g_x[i * DX];
#pragma unroll
    for (int q = 0; q < 4; q++)
        xp[q] = make_float4(xv[4 * q], xv[4 * q + 1], xv[4 * q + 2], xv[4 * q + 3]);

    float hv[H], mg[H];
#pragma unroll
    for (int q = 0; q < 8; q++) {
        hv[4 * q + 0] = hr[q].x; hv[4 * q + 1] = hr[q].y;
        hv[4 * q + 2] = hr[q].z; hv[4 * q + 3] = hr[q].w;
        mg[4 * q + 0] = mr[q].x; mg[4 * q + 1] = mr[q].y;
        mg[4 * q + 2] = mr[q].z; mg[4 * q + 3] = mr[q].w;
    }

    float u[H];
#pragma unroll
    for (int j = 0; j < H; j++) u[j] = nb1[j];
#pragma unroll
    for (int k = 0; k < H; k++) {
        float v = hv[k];
        const float4* w4 = (const float4*)&sN1t[k][0];
#pragma unroll
        for (int q = 0; q < 8; q++) {
            float4 w = w4[q];
            u[4 * q + 0] += w.x * v; u[4 * q + 1] += w.y * v;
            u[4 * q + 2] += w.z * v; u[4 * q + 3] += w.w * v;
        }
    }
#pragma unroll
    for (int k = 0; k < H; k++) {
        float v = mg[k];
        const float4* w4 = (const float4*)&sN1t[H + k][0];
#pragma unroll
        for (int q = 0; q < 8; q++) {
            float4 w = w4[q];
            u[4 * q + 0] += w.x * v; u[4 * q + 1] += w.y * v;
            u[4 * q + 2] += w.z * v; u[4 * q + 3] += w.w * v;
        }
    }
#pragma unroll
    for (int j = 0; j < H; j++) u[j] = silu_f(u[j]);

    float hn[H];
#pragma unroll
    for (int j = 0; j < H; j++) hn[j] = nb2[j];
#pragma unroll
    for (int k = 0; k < H; k++) {
        float v = u[k];
        const float4* w4 = (const float4*)&sN2t[k][0];
#pragma unroll
        for (int q = 0; q < 8; q++) {
            float4 w = w4[q];
            hn[4 * q + 0] += w.x * v; hn[4 * q + 1] += w.y * v;
            hn[4 * q + 2] += w.z * v; hn[4 * q + 3] += w.w * v;
        }
    }
#pragma unroll
    for (int j = 0; j < H; j++) hn[j] += hv[j];
    float4* hp = (float4*)&g_h[i * H];
#pragma unroll
    for (int q = 0; q < 8; q++)
        hp[q] = make_float4(hn[4 * q], hn[4 * q + 1], hn[4 * q + 2], hn[4 * q + 3]);

    if (eW1n) {
        float Av[H], Bv[H];
#pragma unroll
        for (int j = 0; j < H; j++) { Av[j] = eb1n[j]; Bv[j] = 0.0f; }
#pragma unroll
        for (int k = 0; k < H; k++) {
            float v = hn[k];
            const float4* wa = (const float4*)&sEAt[k][0];
            const float4* wb = (const float4*)&sEBt[k][0];
#pragma unroll
            for (int q = 0; q < 8; q++) {
                float4 a = wa[q], b = wb[q];
                Av[4 * q + 0] += a.x * v; Av[4 * q + 1] += a.y * v;
                Av[4 * q + 2] += a.z * v; Av[4 * q + 3] += a.w * v;
                Bv[4 * q + 0] += b.x * v; Bv[4 * q + 1] += b.y * v;
                Bv[4 * q + 2] += b.z * v; Bv[4 * q + 3] += b.w * v;
            }
        }
        float4* Ao = (float4*)&g_A[i * H];
        float4* Bo = (float4*)&g_B[i * H];
#pragma unroll
        for (int q = 0; q < 8; q++) {
            Ao[q] = make_float4(Av[4 * q], Av[4 * q + 1], Av[4 * q + 2], Av[4 * q + 3]);
            Bo[q] = make_float4(Bv[4 * q], Bv[4 * q + 1], Bv[4 * q + 2], Bv[4 * q + 3]);
        }
    }

    if (linW) {
#pragma unroll
        for (int c = 0; c < 3; c++) {
            float acc = 0.0f;
#pragma unroll
            for (int k = 0; k < DX; k++) acc += linW[c * DX + k] * xv[k];
            out[i * 3 + c] = acc;
        }
    }
}

// ---------------------------------------------------------------------------
extern "C" void kernel_launch(void* const* d_in, const int* in_sizes, int n_in,
                              void* d_out, int out_size)
{
    const float* node_attrs = (const float*)d_in[0];
    const float* positions  = (const float*)d_in[1];
    const int*   edge_index = (const int*)  d_in[2];
    const float* proj_W     = (const float*)d_in[3];
    const float* emb_in_W   = (const float*)d_in[4];
    const float* emb_in_b   = (const float*)d_in[5];
    const float* edge_W1    = (const float*)d_in[6];
    const float* edge_b1    = (const float*)d_in[7];
    const float* edge_W2    = (const float*)d_in[8];
    const float* edge_b2    = (const float*)d_in[9];
    const float* node_W1    = (const float*)d_in[10];
    const float* node_b1    = (const float*)d_in[11];
    const float* node_W2    = (const float*)d_in[12];
    const float* node_b2    = (const float*)d_in[13];
    const float* coord_W1   = (const float*)d_in[14];
    const float* coord_b1   = (const float*)d_in[15];
    const float* coord_W2   = (const float*)d_in[16];
    const float* lin_W      = (const float*)d_in[19];

    int n = in_sizes[0] / 3;
    int E = in_sizes[2] / 2;

    float* out = (float*)d_out;

    init_kernel<<<(n + 127) / 128, 128>>>(node_attrs, positions, proj_W,
                                          emb_in_W, emb_in_b,
                                          edge_W1, edge_b1, n);
    hist_kernel<<<(E + 255) / 256, 256>>>(edge_index, E);
    scan_kernel<<<1, SCAN_T>>>(n, E);
    scatter_kernel<<<(E + 255) / 256, 256>>>(edge_index, E);
    nop_kernel<<<1, 32>>>();   // aligns ncu -s 5 onto the first edge_kernel

    for (int l = 0; l < 2; l++) {
        edge_kernel<<<(E + ETPB - 1) / ETPB, ETPB>>>(
            E, positions,
            edge_W1 + l * H * 68,
            edge_W2 + l * H * H, edge_b2 + l * H,
            coord_W1 + l * H * H, coord_b1 + l * H,
            coord_W2 + l * H);

        agg_kernel<<<(n + 3) / 4, 128>>>(n);

        node_kernel<<<(n + NTPB - 1) / NTPB, NTPB>>>(
            node_W1 + l * H * 2 * H, node_b1 + l * H,
            node_W2 + l * H * H,     node_b2 + l * H,
            (l == 0) ? edge_W1 + H * 68 : nullptr,
            (l == 0) ? edge_b1 + H      : nullptr,
            (l == 1) ? lin_W            : nullptr,
            out, n);
    }
}

// round 4
// speedup vs baseline: 1.3245x; 1.3245x over previous
#include <cuda_runtime.h>

// EGNN forward, N=50000, E=1.6M, H=32, DX=16, L=2.
// R4: revert sort (atomic RED scatters); edge MLPs packed with fma.rn.f32x2.

#define H    32
#define DX   16
#define NMAX 50048

typedef unsigned long long u64;

__device__ __align__(16) float g_x[NMAX * DX];
__device__ __align__(16) float g_h[NMAX * H];
__device__ __align__(16) float g_A[NMAX * H];
__device__ __align__(16) float g_B[NMAX * H];
__device__ __align__(16) float g_magg[NMAX * H];
__device__ __align__(16) float g_tagg[NMAX * DX];
__device__ float g_cnt[NMAX];
__device__ int g_dummy;

__device__ __forceinline__ float silu_f(float v) {
    return v * (1.0f / (1.0f + __expf(-v)));
}

// ---- f32x2 packed helpers (Blackwell dual-fp32) -----------------------------
__device__ __forceinline__ u64 pack2(float lo, float hi) {
    u64 r; asm("mov.b64 %0, {%1,%2};" : "=l"(r) : "f"(lo), "f"(hi)); return r;
}
__device__ __forceinline__ u64 dup2(float v) {
    u64 r; asm("mov.b64 %0, {%1,%1};" : "=l"(r) : "f"(v)); return r;
}
__device__ __forceinline__ void unpack2(u64 v, float& lo, float& hi) {
    asm("mov.b64 {%0,%1}, %2;" : "=f"(lo), "=f"(hi) : "l"(v));
}
__device__ __forceinline__ void fma2(u64& d, u64 a, u64 b) {
    asm("fma.rn.f32x2 %0, %1, %2, %0;" : "+l"(d) : "l"(a), "l"(b));
}
__device__ __forceinline__ u64 add2(u64 a, u64 b) {
    u64 r; asm("add.rn.f32x2 %0, %1, %2;" : "=l"(r) : "l"(a), "l"(b)); return r;
}

__device__ __forceinline__ void red_add_v4(float* addr, float a, float b, float c, float d) {
    asm volatile("red.global.add.v4.f32 [%0], {%1,%2,%3,%4};"
                 :: "l"(addr), "f"(a), "f"(b), "f"(c), "f"(d)
                 : "memory");
}

// ---------------------------------------------------------------------------
// init: x0, h0, A0/B0, zero aggregators and counts
// ---------------------------------------------------------------------------
__global__ __launch_bounds__(128, 4) void init_kernel(
    const float* __restrict__ attrs,
    const float* __restrict__ pos,
    const float* __restrict__ projW,
    const float* __restrict__ embW,
    const float* __restrict__ embB,
    const float* __restrict__ eW1,    // layer0 edge_W1 [32][68]
    const float* __restrict__ eb1,
    int n)
{
    __shared__ __align__(16) float sWa[H][H];   // [k][j]
    __shared__ __align__(16) float sWb[H][H];
    for (int idx = threadIdx.x; idx < H * H; idx += 128) {
        int j = idx >> 5, k = idx & 31;
        sWa[k][j] = eW1[j * 68 + k];
        sWb[k][j] = eW1[j * 68 + 32 + k];
    }
    __syncthreads();

    int i = blockIdx.x * 128 + threadIdx.x;
    if (i >= n) return;

    float p0 = pos[i * 3 + 0], p1 = pos[i * 3 + 1], p2 = pos[i * 3 + 2];
    float xv[DX];
#pragma unroll
    for (int j = 0; j < DX; j++)
        xv[j] = projW[j * 3 + 0] * p0 + projW[j * 3 + 1] * p1 + projW[j * 3 + 2] * p2;

    float4* xo = (float4*)&g_x[i * DX];
#pragma unroll
    for (int q = 0; q < 4; q++)
        xo[q] = make_float4(xv[4 * q], xv[4 * q + 1], xv[4 * q + 2], xv[4 * q + 3]);

    float a0 = attrs[i * 3 + 0], a1 = attrs[i * 3 + 1], a2 = attrs[i * 3 + 2];
    float hv[H];
#pragma unroll
    for (int j = 0; j < H; j++)
        hv[j] = embW[j * 3 + 0] * a0 + embW[j * 3 + 1] * a1 + embW[j * 3 + 2] * a2 + embB[j];

    float4* ho = (float4*)&g_h[i * H];
#pragma unroll
    for (int q = 0; q < 8; q++)
        ho[q] = make_float4(hv[4 * q], hv[4 * q + 1], hv[4 * q + 2], hv[4 * q + 3]);

    float Av[H], Bv[H];
#pragma unroll
    for (int j = 0; j < H; j++) { Av[j] = eb1[j]; Bv[j] = 0.0f; }
#pragma unroll
    for (int k = 0; k < H; k++) {
        float hk = hv[k];
        const float4* wa = (const float4*)&sWa[k][0];
        const float4* wb = (const float4*)&sWb[k][0];
#pragma unroll
        for (int q = 0; q < 8; q++) {
            float4 a = wa[q], b = wb[q];
            Av[4 * q + 0] += a.x * hk; Av[4 * q + 1] += a.y * hk;
            Av[4 * q + 2] += a.z * hk; Av[4 * q + 3] += a.w * hk;
            Bv[4 * q + 0] += b.x * hk; Bv[4 * q + 1] += b.y * hk;
            Bv[4 * q + 2] += b.z * hk; Bv[4 * q + 3] += b.w * hk;
        }
    }
    float4* Ao = (float4*)&g_A[i * H];
    float4* Bo = (float4*)&g_B[i * H];
#pragma unroll
    for (int q = 0; q < 8; q++) {
        Ao[q] = make_float4(Av[4 * q], Av[4 * q + 1], Av[4 * q + 2], Av[4 * q + 3]);
        Bo[q] = make_float4(Bv[4 * q], Bv[4 * q + 1], Bv[4 * q + 2], Bv[4 * q + 3]);
    }

    const float4 z4 = make_float4(0.f, 0.f, 0.f, 0.f);
    float4* mz = (float4*)&g_magg[i * H];
    float4* tz = (float4*)&g_tagg[i * DX];
#pragma unroll
    for (int q = 0; q < 8; q++) mz[q] = z4;
#pragma unroll
    for (int q = 0; q < 4; q++) tz[q] = z4;
    g_cnt[i] = 0.0f;
}

// ---------------------------------------------------------------------------
__global__ void count_kernel(const int* __restrict__ ei, int E)
{
    int e = blockIdx.x * blockDim.x + threadIdx.x;
    if (e < E) atomicAdd(&g_cnt[ei[e]], 1.0f);
}

// nop: slot alignment so ncu lands on an edge kernel (slots 4 and 6)
__global__ void nop_kernel() { if (blockIdx.x == 1u << 30) g_dummy = 1; }

// ---------------------------------------------------------------------------
// edge kernel: f32x2-packed fused MLPs + coord head, vector RED scatters
// ---------------------------------------------------------------------------
#define ETPB 128
#define HQ   (H / 2)   // 16 packed pairs

__global__ __launch_bounds__(ETPB) void edge_kernel(
    const int* __restrict__ ei, int E,
    const float* __restrict__ pos,
    const float* __restrict__ W1,   // [32][68], cols 64..67 used
    const float* __restrict__ W2,   // [32][32]
    const float* __restrict__ b2,
    const float* __restrict__ cW1,  // [32][32]
    const float* __restrict__ cb1,
    const float* __restrict__ cW2)  // [32]
{
    // weights pre-paired along j: s[k][jq] = (w[2jq][k], w[2jq+1][k])
    __shared__ __align__(16) u64 s_W2t[H][HQ];
    __shared__ __align__(16) u64 s_cW1t[H][HQ];
    __shared__ u64 s_wr2[HQ];
    __shared__ u64 s_we2[3][HQ];
    __shared__ u64 s_b22[HQ];
    __shared__ u64 s_cb12[HQ];
    __shared__ float s_cw2[H];

    for (int idx = threadIdx.x; idx < H * HQ; idx += ETPB) {
        int k = idx & 31, jq = idx >> 5;
        s_W2t[k][jq]  = pack2(W2[(2 * jq) * H + k],  W2[(2 * jq + 1) * H + k]);
        s_cW1t[k][jq] = pack2(cW1[(2 * jq) * H + k], cW1[(2 * jq + 1) * H + k]);
    }
    if (threadIdx.x < HQ) {
        int jq = threadIdx.x;
        s_wr2[jq]    = pack2(W1[(2 * jq) * 68 + 64], W1[(2 * jq + 1) * 68 + 64]);
        s_we2[0][jq] = pack2(W1[(2 * jq) * 68 + 65], W1[(2 * jq + 1) * 68 + 65]);
        s_we2[1][jq] = pack2(W1[(2 * jq) * 68 + 66], W1[(2 * jq + 1) * 68 + 66]);
        s_we2[2][jq] = pack2(W1[(2 * jq) * 68 + 67], W1[(2 * jq + 1) * 68 + 67]);
        s_b22[jq]    = pack2(b2[2 * jq],  b2[2 * jq + 1]);
        s_cb12[jq]   = pack2(cb1[2 * jq], cb1[2 * jq + 1]);
    }
    if (threadIdx.x < H) s_cw2[threadIdx.x] = cW2[threadIdx.x];
    __syncthreads();

    int e = blockIdx.x * ETPB + threadIdx.x;
    if (e >= E) return;

    int row = ei[e];
    int col = ei[E + e];

    float ea0 = pos[row * 3 + 0] - pos[col * 3 + 0];
    float ea1 = pos[row * 3 + 1] - pos[col * 3 + 1];
    float ea2 = pos[row * 3 + 2] - pos[col * 3 + 2];

    float cd[DX];
    const float4* xr = (const float4*)&g_x[row * DX];
    const float4* xc = (const float4*)&g_x[col * DX];
    float radial = 0.0f;
#pragma unroll
    for (int q = 0; q < 4; q++) {
        float4 a = xr[q], b = xc[q];
        float d0 = a.x - b.x, d1 = a.y - b.y, d2 = a.z - b.z, d3 = a.w - b.w;
        cd[4 * q + 0] = d0; cd[4 * q + 1] = d1; cd[4 * q + 2] = d2; cd[4 * q + 3] = d3;
        radial += d0 * d0 + d1 * d1 + d2 * d2 + d3 * d3;
    }

    // ---- layer 1 (A/B factored), packed -------------------------------
    float acc[H];   // scalar post-silu values (multiplicands for layer 2)
    {
        const ulonglong2* Ar = (const ulonglong2*)&g_A[row * H];
        const ulonglong2* Bc = (const ulonglong2*)&g_B[col * H];
        u64 acc2[HQ];
#pragma unroll
        for (int q = 0; q < 8; q++) {
            ulonglong2 a = Ar[q], b = Bc[q];
            acc2[2 * q + 0] = add2(a.x, b.x);
            acc2[2 * q + 1] = add2(a.y, b.y);
        }
        u64 rad2 = dup2(radial);
        u64 e02 = dup2(ea0), e12 = dup2(ea1), e22 = dup2(ea2);
#pragma unroll
        for (int jq = 0; jq < HQ; jq++) {
            fma2(acc2[jq], s_wr2[jq], rad2);
            fma2(acc2[jq], s_we2[0][jq], e02);
            fma2(acc2[jq], s_we2[1][jq], e12);
            fma2(acc2[jq], s_we2[2][jq], e22);
        }
#pragma unroll
        for (int jq = 0; jq < HQ; jq++) {
            float lo, hi;
            unpack2(acc2[jq], lo, hi);
            acc[2 * jq + 0] = silu_f(lo);
            acc[2 * jq + 1] = silu_f(hi);
        }
    }

    // ---- layer 2: m = silu(W2 m1 + b2), packed -------------------------
    float m[H];
    {
        u64 m2[HQ];
#pragma unroll
        for (int jq = 0; jq < HQ; jq++) m2[jq] = s_b22[jq];
#pragma unroll
        for (int k = 0; k < H; k++) {
            u64 mk2 = dup2(acc[k]);
            const ulonglong2* w4 = (const ulonglong2*)&s_W2t[k][0];
#pragma unroll
            for (int q = 0; q < 8; q++) {
                ulonglong2 w = w4[q];
                fma2(m2[2 * q + 0], w.x, mk2);
                fma2(m2[2 * q + 1], w.y, mk2);
            }
        }
#pragma unroll
        for (int jq = 0; jq < HQ; jq++) {
            float lo, hi;
            unpack2(m2[jq], lo, hi);
            m[2 * jq + 0] = silu_f(lo);
            m[2 * jq + 1] = silu_f(hi);
        }
    }

    // ---- coord head, packed --------------------------------------------
    float cm;
    {
        u64 c2[HQ];
#pragma unroll
        for (int jq = 0; jq < HQ; jq++) c2[jq] = s_cb12[jq];
#pragma unroll
        for (int k = 0; k < H; k++) {
            u64 mk2 = dup2(m[k]);
            const ulonglong2* w4 = (const ulonglong2*)&s_cW1t[k][0];
#pragma unroll
            for (int q = 0; q < 8; q++) {
                ulonglong2 w = w4[q];
                fma2(c2[2 * q + 0], w.x, mk2);
                fma2(c2[2 * q + 1], w.y, mk2);
            }
        }
        cm = 0.0f;
#pragma unroll
        for (int jq = 0; jq < HQ; jq++) {
            float lo, hi;
            unpack2(c2[jq], lo, hi);
            cm += s_cw2[2 * jq + 0] * silu_f(lo);
            cm += s_cw2[2 * jq + 1] * silu_f(hi);
        }
    }

    float* mago = &g_magg[row * H];
#pragma unroll
    for (int q = 0; q < 8; q++)
        red_add_v4(mago + 4 * q, m[4 * q], m[4 * q + 1], m[4 * q + 2], m[4 * q + 3]);

    float* tago = &g_tagg[row * DX];
#pragma unroll
    for (int q = 0; q < 4; q++)
        red_add_v4(tago + 4 * q,
                   cd[4 * q] * cm, cd[4 * q + 1] * cm, cd[4 * q + 2] * cm, cd[4 * q + 3] * cm);
}

// ---------------------------------------------------------------------------
// node kernel (early gathers; zeroes aggregators for the next layer/replay)
// ---------------------------------------------------------------------------
#define NTPB 128

__global__ __launch_bounds__(NTPB, 4) void node_kernel(
    const float* __restrict__ nW1,   // [32][64]
    const float* __restrict__ nb1,
    const float* __restrict__ nW2,   // [32][32]
    const float* __restrict__ nb2,
    const float* __restrict__ eW1n,  // next-layer edge_W1 [32][68] or null
    const float* __restrict__ eb1n,
    const float* __restrict__ linW,  // [3][16] or null
    float* __restrict__ out,
    int n)
{
    __shared__ __align__(16) float sN1t[2 * H][H];  // [k][j]
    __shared__ __align__(16) float sN2t[H][H];
    __shared__ __align__(16) float sEAt[H][H];
    __shared__ __align__(16) float sEBt[H][H];

    int i = blockIdx.x * NTPB + threadIdx.x;
    bool active = (i < n);

    float cnt = 0.f;
    float4 xr[4], tr[4], hr[8], mr[8];
    if (active) {
        cnt = g_cnt[i];
        const float4* xp = (const float4*)&g_x[i * DX];
        const float4* tp = (const float4*)&g_tagg[i * DX];
        const float4* hp = (const float4*)&g_h[i * H];
        const float4* mp = (const float4*)&g_magg[i * H];
#pragma unroll
        for (int q = 0; q < 4; q++) { xr[q] = xp[q]; tr[q] = tp[q]; }
#pragma unroll
        for (int q = 0; q < 8; q++) { hr[q] = hp[q]; mr[q] = mp[q]; }
    }

    for (int idx = threadIdx.x; idx < H * 2 * H; idx += NTPB) {
        int j = idx >> 6, k = idx & 63;
        sN1t[k][j] = nW1[idx];
    }
    for (int idx = threadIdx.x; idx < H * H; idx += NTPB) {
        int j = idx >> 5, k = idx & 31;
        sN2t[k][j] = nW2[idx];
        if (eW1n) {
            sEAt[k][j] = eW1n[j * 68 + k];
            sEBt[k][j] = eW1n[j * 68 + 32 + k];
        }
    }
    __syncthreads();

    if (!active) return;

    float inv = 1.0f / fmaxf(cnt, 1.0f);
    const float4 z4 = make_float4(0.f, 0.f, 0.f, 0.f);

    float xv[DX];
#pragma unroll
    for (int q = 0; q < 4; q++) {
        xv[4 * q + 0] = xr[q].x + tr[q].x * inv;
        xv[4 * q + 1] = xr[q].y + tr[q].y * inv;
        xv[4 * q + 2] = xr[q].z + tr[q].z * inv;
        xv[4 * q + 3] = xr[q].w + tr[q].w * inv;
    }
    float4* xp = (float4*)&g_x[i * DX];
    float4* tp = (float4*)&g_tagg[i * DX];
#pragma unroll
    for (int q = 0; q < 4; q++) {
        xp[q] = make_float4(xv[4 * q], xv[4 * q + 1], xv[4 * q + 2], xv[4 * q + 3]);
        tp[q] = z4;
    }

    float hv[H], mg[H];
    float4* mp = (float4*)&g_magg[i * H];
#pragma unroll
    for (int q = 0; q < 8; q++) {
        hv[4 * q + 0] = hr[q].x; hv[4 * q + 1] = hr[q].y;
        hv[4 * q + 2] = hr[q].z; hv[4 * q + 3] = hr[q].w;
        mg[4 * q + 0] = mr[q].x; mg[4 * q + 1] = mr[q].y;
        mg[4 * q + 2] = mr[q].z; mg[4 * q + 3] = mr[q].w;
        mp[q] = z4;
    }

    float u[H];
#pragma unroll
    for (int j = 0; j < H; j++) u[j] = nb1[j];
#pragma unroll
    for (int k = 0; k < H; k++) {
        float v = hv[k];
        const float4* w4 = (const float4*)&sN1t[k][0];
#pragma unroll
        for (int q = 0; q < 8; q++) {
            float4 w = w4[q];
            u[4 * q + 0] += w.x * v; u[4 * q + 1] += w.y * v;
            u[4 * q + 2] += w.z * v; u[4 * q + 3] += w.w * v;
        }
    }
#pragma unroll
    for (int k = 0; k < H; k++) {
        float v = mg[k];
        const float4* w4 = (const float4*)&sN1t[H + k][0];
#pragma unroll
        for (int q = 0; q < 8; q++) {
            float4 w = w4[q];
            u[4 * q + 0] += w.x * v; u[4 * q + 1] += w.y * v;
            u[4 * q + 2] += w.z * v; u[4 * q + 3] += w.w * v;
        }
    }
#pragma unroll
    for (int j = 0; j < H; j++) u[j] = silu_f(u[j]);

    float hn[H];
#pragma unroll
    for (int j = 0; j < H; j++) hn[j] = nb2[j];
#pragma unroll
    for (int k = 0; k < H; k++) {
        float v = u[k];
        const float4* w4 = (const float4*)&sN2t[k][0];
#pragma unroll
        for (int q = 0; q < 8; q++) {
            float4 w = w4[q];
            hn[4 * q + 0] += w.x * v; hn[4 * q + 1] += w.y * v;
            hn[4 * q + 2] += w.z * v; hn[4 * q + 3] += w.w * v;
        }
    }
#pragma unroll
    for (int j = 0; j < H; j++) hn[j] += hv[j];
    float4* hp = (float4*)&g_h[i * H];
#pragma unroll
    for (int q = 0; q < 8; q++)
        hp[q] = make_float4(hn[4 * q], hn[4 * q + 1], hn[4 * q + 2], hn[4 * q + 3]);

    if (eW1n) {
        float Av[H], Bv[H];
#pragma unroll
        for (int j = 0; j < H; j++) { Av[j] = eb1n[j]; Bv[j] = 0.0f; }
#pragma unroll
        for (int k = 0; k < H; k++) {
            float v = hn[k];
            const float4* wa = (const float4*)&sEAt[k][0];
            const float4* wb = (const float4*)&sEBt[k][0];
#pragma unroll
            for (int q = 0; q < 8; q++) {
                float4 a = wa[q], b = wb[q];
                Av[4 * q + 0] += a.x * v; Av[4 * q + 1] += a.y * v;
                Av[4 * q + 2] += a.z * v; Av[4 * q + 3] += a.w * v;
                Bv[4 * q + 0] += b.x * v; Bv[4 * q + 1] += b.y * v;
                Bv[4 * q + 2] += b.z * v; Bv[4 * q + 3] += b.w * v;
            }
        }
        float4* Ao = (float4*)&g_A[i * H];
        float4* Bo = (float4*)&g_B[i * H];
#pragma unroll
        for (int q = 0; q < 8; q++) {
            Ao[q] = make_float4(Av[4 * q], Av[4 * q + 1], Av[4 * q + 2], Av[4 * q + 3]);
            Bo[q] = make_float4(Bv[4 * q], Bv[4 * q + 1], Bv[4 * q + 2], Bv[4 * q + 3]);
        }
    }

    if (linW) {
#pragma unroll
        for (int c = 0; c < 3; c++) {
            float acc = 0.0f;
#pragma unroll
            for (int k = 0; k < DX; k++) acc += linW[c * DX + k] * xv[k];
            out[i * 3 + c] = acc;
        }
    }
}

// ---------------------------------------------------------------------------
extern "C" void kernel_launch(void* const* d_in, const int* in_sizes, int n_in,
                              void* d_out, int out_size)
{
    const float* node_attrs = (const float*)d_in[0];
    const float* positions  = (const float*)d_in[1];
    const int*   edge_index = (const int*)  d_in[2];
    const float* proj_W     = (const float*)d_in[3];
    const float* emb_in_W   = (const float*)d_in[4];
    const float* emb_in_b   = (const float*)d_in[5];
    const float* edge_W1    = (const float*)d_in[6];
    const float* edge_b1    = (const float*)d_in[7];
    const float* edge_W2    = (const float*)d_in[8];
    const float* edge_b2    = (const float*)d_in[9];
    const float* node_W1    = (const float*)d_in[10];
    const float* node_b1    = (const float*)d_in[11];
    const float* node_W2    = (const float*)d_in[12];
    const float* node_b2    = (const float*)d_in[13];
    const float* coord_W1   = (const float*)d_in[14];
    const float* coord_b1   = (const float*)d_in[15];
    const float* coord_W2   = (const float*)d_in[16];
    const float* lin_W      = (const float*)d_in[19];

    int n = in_sizes[0] / 3;
    int E = in_sizes[2] / 2;

    float* out = (float*)d_out;

    init_kernel<<<(n + 127) / 128, 128>>>(node_attrs, positions, proj_W,
                                          emb_in_W, emb_in_b,
                                          edge_W1, edge_b1, n);   // launch 1
    count_kernel<<<(E + 255) / 256, 256>>>(edge_index, E);        // launch 2
    nop_kernel<<<1, 32>>>();                                      // launch 3

    for (int l = 0; l < 2; l++) {
        edge_kernel<<<(E + ETPB - 1) / ETPB, ETPB>>>(             // launches 4, 6
            edge_index, E, positions,
            edge_W1 + l * H * 68,
            edge_W2 + l * H * H, edge_b2 + l * H,
            coord_W1 + l * H * H, coord_b1 + l * H,
            coord_W2 + l * H);

        node_kernel<<<(n + NTPB - 1) / NTPB, NTPB>>>(             // launches 5, 7
            node_W1 + l * H * 2 * H, node_b1 + l * H,
            node_W2 + l * H * H,     node_b2 + l * H,
            (l == 0) ? edge_W1 + H * 68 : nullptr,
            (l == 0) ? edge_b1 + H      : nullptr,
            (l == 1) ? lin_W            : nullptr,
            out, n);
    }
}